// round 16
// baseline (speedup 1.0000x reference)
#include <cuda_runtime.h>
#include <cuda_bf16.h>

// Problem constants:
//   T=4 tables, E=1,000,000 rows/table, D=128 dim, B=8192 bags, L=32 bag length
//   indices: [T, B, L] int32 (1,048,576 elems)
//   weights: [T, E, D] float32 (512,000,000 elems)
//   output:  [B, T*D] float32: out[b, t*D + d] = sum_l weights[t, indices[t,b,l], d]
//
// Design (R5-R15 converged + R16 experiment):
//   - One warp per (t,b) bag.
//   - NEW: 256-bit gathers (ld.global.nc.v8.f32, sm_100+). 16 lanes x 32B
//     cover one 512B row, so each LDG.256 fetches TWO full rows per warp:
//     half = lane>>4 selects which of a row pair, sub = lane&15 selects the
//     32B chunk. 16 load instructions cover all L=32 rows (vs 32 LDG.128),
//     halving LSU/L1tex instruction pressure per byte.
//   - Epilogue: halves hold partial sums over even/odd rows -> 8x shfl.xor(16)
//     + adds, then lanes 0-15 store the full row as 256-bit streaming stores.
//   - Indices: one int32/lane, __ldcs (read-once), shuffle-broadcast.
//   - Flat 4096-CTA grid (persistent grid measured -10us in R13).
//   - __launch_bounds__(256,2): 128-reg budget guarantees the 64-reg load
//     buffer never spills; occupancy 16 warps/SM is past sufficiency
//     (R7/R10: 30% occ already saturates DRAM).

#define T_TABLES 4
#define E_ROWS   1000000
#define D_DIM    128
#define B_BATCH  8192
#define L_BAG    32
#define BATCH    8   // LDG.256s buffered per stage (8 x 8 floats = 64 regs)

struct f8 { float v[8]; };

__device__ __forceinline__ f8 ldg256(const float* p) {
    f8 r;
    asm volatile("ld.global.nc.v8.f32 {%0,%1,%2,%3,%4,%5,%6,%7}, [%8];"
                 : "=f"(r.v[0]), "=f"(r.v[1]), "=f"(r.v[2]), "=f"(r.v[3]),
                   "=f"(r.v[4]), "=f"(r.v[5]), "=f"(r.v[6]), "=f"(r.v[7])
                 : "l"(p));
    return r;
}

__device__ __forceinline__ void stg256_cs(float* p, const f8& r) {
    asm volatile("st.global.cs.v8.f32 [%0], {%1,%2,%3,%4,%5,%6,%7,%8};"
                 :: "l"(p),
                    "f"(r.v[0]), "f"(r.v[1]), "f"(r.v[2]), "f"(r.v[3]),
                    "f"(r.v[4]), "f"(r.v[5]), "f"(r.v[6]), "f"(r.v[7])
                 : "memory");
}

__global__ __launch_bounds__(256, 2)
void embedding_bag_sum_kernel(const int* __restrict__ indices,
                              const float* __restrict__ weights,
                              float* __restrict__ out)
{
    const int gtid = blockIdx.x * blockDim.x + threadIdx.x;
    const int warp = gtid >> 5;               // 0 .. T*B-1 (grid is exact)
    const int lane = threadIdx.x & 31;
    const int half = lane >> 4;               // which row of each pair
    const int sub  = lane & 15;               // 32B chunk within the row

    const int t = warp >> 13;                 // warp / B  (B = 8192 = 2^13)
    const int b = warp & (B_BATCH - 1);       // warp % B

    // Read-once index vector: streaming load (evict-first), one per lane.
    const int* bag = indices + ((size_t)t * B_BATCH + b) * L_BAG;
    int my_idx = __ldcs(bag + lane);
    // Clamp once per lane: malformed index degrades to rel_err, not a crash.
    if ((unsigned)my_idx >= (unsigned)E_ROWS) my_idx = 0;

    const float* wt = weights + (size_t)t * E_ROWS * D_DIM;

    float acc[8];
    #pragma unroll
    for (int i = 0; i < 8; ++i) acc[i] = 0.f;

    // 16 row-pairs: pair p covers bag slots (2p + half).
    #pragma unroll
    for (int stage = 0; stage < (L_BAG / 2) / BATCH; ++stage) {
        f8 v[BATCH];
        #pragma unroll
        for (int j = 0; j < BATCH; ++j) {
            const int p = stage * BATCH + j;
            int row = __shfl_sync(0xffffffffu, my_idx, 2 * p + half);
            v[j] = ldg256(wt + (size_t)row * D_DIM + sub * 8);
        }
        #pragma unroll
        for (int j = 0; j < BATCH; ++j)
            #pragma unroll
            for (int i = 0; i < 8; ++i)
                acc[i] += v[j].v[i];
    }

    // Cross-half reduction: lane k and k^16 hold partial sums of the same
    // 32B chunk over the two row-slot parities.
    f8 total;
    #pragma unroll
    for (int i = 0; i < 8; ++i)
        total.v[i] = acc[i] + __shfl_xor_sync(0xffffffffu, acc[i], 16);

    // out[b, t*D + :]: lanes 0-15 store 32B each (512B coalesced, evict-first).
    if (half == 0) {
        float* op = out + (size_t)b * (T_TABLES * D_DIM) + t * D_DIM + sub * 8;
        stg256_cs(op, total);
    }
}

extern "C" void kernel_launch(void* const* d_in, const int* in_sizes, int n_in,
                              void* d_out, int out_size)
{
    // Identify inputs by element count (robust to metadata ordering):
    //   indices: T*B*L = 1,048,576 ; weights: T*E*D = 512,000,000
    const int*   indices;
    const float* weights;
    if (in_sizes[0] < in_sizes[1]) {
        indices = (const int*)d_in[0];
        weights = (const float*)d_in[1];
    } else {
        indices = (const int*)d_in[1];
        weights = (const float*)d_in[0];
    }
    float* out = (float*)d_out;

    const int total_warps = T_TABLES * B_BATCH;           // 32768
    const int threads     = 256;                          // 8 warps/CTA
    const int blocks      = (total_warps * 32) / threads; // 4096

    embedding_bag_sum_kernel<<<blocks, threads>>>(indices, weights, out);
}